// round 16
// baseline (speedup 1.0000x reference)
#include <cuda_runtime.h>
#include <math.h>
#include <stdint.h>

#define B_   4
#define N_   8192
#define D_   1024
#define H_   16
#define DH_  64
#define NQ_  1024
#define NKV_ 2048
#define KVR_ 2049   // NKV + 1 null row

// ---------------------------------------------------------------- device scratch (no allocations allowed)
__device__ float g_logits[2 * B_ * N_];          // [router][b][n]
__device__ int   g_selidx[2 * B_ * NKV_];        // [router][b][k] (router 0 uses first NQ_)
__device__ float g_q [B_ * NQ_ * D_];            // [b][i][h*64+d], rotary applied in place
__device__ float g_k [B_ * H_ * KVR_ * DH_];     // [b*16+h][row][d], row 0 = null
__device__ float g_v [B_ * H_ * KVR_ * DH_];
__device__ float g_ao[B_ * NQ_ * D_];            // attention output [b][i][h*64+d]

// ================================================================ 1. router logits (warp per token, both routers)
__global__ __launch_bounds__(256) void k_router(const float* __restrict__ x,
                                                const float* __restrict__ wrq,
                                                const float* __restrict__ wrk)
{
    int gw   = (blockIdx.x * blockDim.x + threadIdx.x) >> 5;   // token index over B*N
    int lane = threadIdx.x & 31;
    if (gw >= B_ * N_) return;
    const float4* xr  = (const float4*)(x + (size_t)gw * D_);
    const float4* wq4 = (const float4*)wrq;
    const float4* wk4 = (const float4*)wrk;
    float aq = 0.f, ak = 0.f;
    #pragma unroll 4
    for (int i = lane; i < D_ / 4; i += 32) {
        float4 xv = xr[i], q = wq4[i], k = wk4[i];
        aq += xv.x * q.x + xv.y * q.y + xv.z * q.z + xv.w * q.w;
        ak += xv.x * k.x + xv.y * k.y + xv.z * k.z + xv.w * k.w;
    }
    #pragma unroll
    for (int o = 16; o; o >>= 1) {
        aq += __shfl_xor_sync(0xffffffffu, aq, o);
        ak += __shfl_xor_sync(0xffffffffu, ak, o);
    }
    if (!lane) { g_logits[gw] = aq; g_logits[B_ * N_ + gw] = ak; }
}

// ================================================================ 2. coordinate descent + exact top-k selection
// one block per (router, batch) row: 8 blocks x 1024 threads, 48KB static smem
__global__ __launch_bounds__(1024) void k_coorsel()
{
    __shared__ __align__(16) unsigned char smraw[49152];
    unsigned int*   skey = (unsigned int*)smraw;              // 8192 u32 score bits (32KB)
    unsigned short* sidx = (unsigned short*)(smraw + 32768);  // 8192 u16 idx (16KB)
    float*          red  = (float*)smraw;                     // scratch during descent (aliases skey)

    int r = blockIdx.x >> 2;
    int b = blockIdx.x & 3;
    int ksel = r ? NKV_ : NQ_;
    int keff = r ? 2304 : 1152;               // int(num_tokens * 9/8)
    float cst = 0.1f * logf((float)keff);
    const float* lg = g_logits + ((size_t)r * B_ + b) * N_;
    int t = threadIdx.x;

    float sreg[8], breg[8];
    #pragma unroll
    for (int j = 0; j < 8; j++) { float v = lg[t + j * 1024]; sreg[j] = v; breg[j] = -v; }

    float a = 0.f;
    for (int it = 0; it < 20; it++) {
        float arg[8];
        float mloc = -INFINITY;
        #pragma unroll
        for (int j = 0; j < 8; j++) { arg[j] = (sreg[j] + breg[j]) / 0.1f; mloc = fmaxf(mloc, arg[j]); }
        #pragma unroll
        for (int o = 16; o; o >>= 1) mloc = fmaxf(mloc, __shfl_xor_sync(0xffffffffu, mloc, o));
        if (!(t & 31)) red[t >> 5] = mloc;
        __syncthreads();
        if (t < 32) {
            float v = red[t];
            #pragma unroll
            for (int o = 16; o; o >>= 1) v = fmaxf(v, __shfl_xor_sync(0xffffffffu, v, o));
            if (!t) red[32] = v;
        }
        __syncthreads();
        float m = red[32];
        __syncthreads();

        float sl = 0.f;
        #pragma unroll
        for (int j = 0; j < 8; j++) sl += expf(arg[j] - m);
        #pragma unroll
        for (int o = 16; o; o >>= 1) sl += __shfl_xor_sync(0xffffffffu, sl, o);
        if (!(t & 31)) red[t >> 5] = sl;
        __syncthreads();
        if (t < 32) {
            float v = red[t];
            #pragma unroll
            for (int o = 16; o; o >>= 1) v += __shfl_xor_sync(0xffffffffu, v, o);
            if (!t) red[32] = v;
        }
        __syncthreads();
        float sum = red[32];
        __syncthreads();   // red reused / aliased below

        a = cst - 0.1f * (logf(sum) + m);
        #pragma unroll
        for (int j = 0; j < 8; j++) breg[j] = -fmaxf(sreg[j] + a, 0.f);
    }

    // final scores (match JAX op order: exp(((s+a)+b)/EPS)); positive floats -> uint order == float order
    #pragma unroll
    for (int j = 0; j < 8; j++) {
        float sc = expf(((sreg[j] + a) + breg[j]) / 0.1f);
        int gi = t + j * 1024;
        skey[gi] = __float_as_uint(sc);
        sidx[gi] = (unsigned short)gi;
    }
    __syncthreads();

    // bitonic sort descending by (score, then index ascending) — exact jax.lax.top_k tie-break
    for (int k = 2; k <= 8192; k <<= 1) {
        for (int jj = k >> 1; jj > 0; jj >>= 1) {
            for (int i = t; i < 8192; i += 1024) {
                int ixj = i ^ jj;
                if (ixj > i) {
                    unsigned int   k1 = skey[i], k2 = skey[ixj];
                    unsigned short i1 = sidx[i], i2 = sidx[ixj];
                    bool gt2 = (k2 > k1) || (k2 == k1 && i2 < i1);   // elem[ixj] ranks before elem[i]
                    if (gt2 == ((i & k) == 0)) {
                        skey[i] = k2; skey[ixj] = k1;
                        sidx[i] = i2; sidx[ixj] = i1;
                    }
                }
            }
            __syncthreads();
        }
    }

    int* dst = g_selidx + ((size_t)r * B_ + b) * NKV_;
    for (int i = t; i < ksel; i += 1024) dst[i] = (int)sidx[i];
}

// ================================================================ 3. fill output with null tokens
__global__ void k_fillout(float4* __restrict__ out4, const float* __restrict__ nt)
{
    const float4* nt4 = (const float4*)nt;
    int total = B_ * N_ * (D_ / 4);
    for (int i = blockIdx.x * blockDim.x + threadIdx.x; i < total; i += gridDim.x * blockDim.x)
        out4[i] = nt4[i & 255];
}

// ================================================================ GEMM kernels: 64x64 tile, BK=16, 256 thr, 4x4/thread
__global__ __launch_bounds__(256) void k_qproj(const float* __restrict__ x, const float* __restrict__ wq)
{
    __shared__ float As[16][68];
    __shared__ float Bs[16][68];
    __shared__ int rows[64];
    int bn = blockIdx.x, bm = blockIdx.y, b = blockIdx.z;
    int tid = threadIdx.x;
    int ty = tid >> 4, tx = tid & 15;
    if (tid < 64) rows[tid] = g_selidx[b * NKV_ + bm * 64 + tid];
    __syncthreads();
    int lar = tid >> 2, lac = (tid & 3) * 4;
    int lbr = tid >> 4, lbc = (tid & 15) * 4;
    const float* arow = x + ((size_t)b * N_ + rows[lar]) * D_ + lac;
    const float* brow = wq + (size_t)lbr * 1024 + bn * 64 + lbc;
    float acc[4][4] = {};
    for (int k0 = 0; k0 < 1024; k0 += 16) {
        float4 av = *(const float4*)(arow + k0);
        As[lac + 0][lar] = av.x; As[lac + 1][lar] = av.y; As[lac + 2][lar] = av.z; As[lac + 3][lar] = av.w;
        *(float4*)&Bs[lbr][lbc] = *(const float4*)(brow + (size_t)k0 * 1024);
        __syncthreads();
        #pragma unroll
        for (int kk = 0; kk < 16; kk++) {
            float4 a4 = *(const float4*)&As[kk][ty * 4];
            float4 b4 = *(const float4*)&Bs[kk][tx * 4];
            float aa[4] = {a4.x, a4.y, a4.z, a4.w};
            float bb[4] = {b4.x, b4.y, b4.z, b4.w};
            #pragma unroll
            for (int i = 0; i < 4; i++)
                #pragma unroll
                for (int j = 0; j < 4; j++) acc[i][j] += aa[i] * bb[j];
        }
        __syncthreads();
    }
    #pragma unroll
    for (int i = 0; i < 4; i++) {
        float4 w = make_float4(acc[i][0], acc[i][1], acc[i][2], acc[i][3]);
        *(float4*)&g_q[((size_t)(b * NQ_ + bm * 64 + ty * 4 + i)) * D_ + bn * 64 + tx * 4] = w;
    }
}

__global__ __launch_bounds__(256) void k_kvproj(const float* __restrict__ x, const float* __restrict__ wkv)
{
    __shared__ float As[16][68];
    __shared__ float Bs[16][68];
    __shared__ int rows[64];
    int bn = blockIdx.x, bm = blockIdx.y, b = blockIdx.z;
    int tid = threadIdx.x;
    int ty = tid >> 4, tx = tid & 15;
    if (tid < 64) rows[tid] = g_selidx[(B_ + b) * NKV_ + bm * 64 + tid];
    __syncthreads();
    int lar = tid >> 2, lac = (tid & 3) * 4;
    int lbr = tid >> 4, lbc = (tid & 15) * 4;
    const float* arow = x + ((size_t)b * N_ + rows[lar]) * D_ + lac;
    const float* brow = wkv + (size_t)lbr * 2048 + bn * 64 + lbc;
    float acc[4][4] = {};
    for (int k0 = 0; k0 < 1024; k0 += 16) {
        float4 av = *(const float4*)(arow + k0);
        As[lac + 0][lar] = av.x; As[lac + 1][lar] = av.y; As[lac + 2][lar] = av.z; As[lac + 3][lar] = av.w;
        *(float4*)&Bs[lbr][lbc] = *(const float4*)(brow + (size_t)k0 * 2048);
        __syncthreads();
        #pragma unroll
        for (int kk = 0; kk < 16; kk++) {
            float4 a4 = *(const float4*)&As[kk][ty * 4];
            float4 b4 = *(const float4*)&Bs[kk][tx * 4];
            float aa[4] = {a4.x, a4.y, a4.z, a4.w};
            float bb[4] = {b4.x, b4.y, b4.z, b4.w};
            #pragma unroll
            for (int i = 0; i < 4; i++)
                #pragma unroll
                for (int j = 0; j < 4; j++) acc[i][j] += aa[i] * bb[j];
        }
        __syncthreads();
    }
    // column tile bn covers e = bn*64..+63 of (2,H,DH): s = bn>>4, h = bn&15, d = tile col
    int s = bn >> 4, h = bn & 15;
    float* dstm = (s ? g_v : g_k);
    #pragma unroll
    for (int i = 0; i < 4; i++) {
        float4 w = make_float4(acc[i][0], acc[i][1], acc[i][2], acc[i][3]);
        *(float4*)&dstm[(((size_t)(b * H_ + h)) * KVR_ + 1 + bm * 64 + ty * 4 + i) * DH_ + tx * 4] = w;
    }
}

__global__ __launch_bounds__(256) void k_outproj(const float* __restrict__ wout, float* __restrict__ out)
{
    __shared__ float As[16][68];
    __shared__ float Bs[16][68];
    __shared__ int rows[64];
    int bn = blockIdx.x, bm = blockIdx.y, b = blockIdx.z;
    int tid = threadIdx.x;
    int ty = tid >> 4, tx = tid & 15;
    if (tid < 64) rows[tid] = g_selidx[b * NKV_ + bm * 64 + tid];   // q router indices for scatter
    __syncthreads();
    int lar = tid >> 2, lac = (tid & 3) * 4;
    int lbr = tid >> 4, lbc = (tid & 15) * 4;
    const float* arow = g_ao + ((size_t)b * NQ_ + bm * 64 + lar) * D_ + lac;
    const float* brow = wout + (size_t)lbr * 1024 + bn * 64 + lbc;
    float acc[4][4] = {};
    for (int k0 = 0; k0 < 1024; k0 += 16) {
        float4 av = *(const float4*)(arow + k0);
        As[lac + 0][lar] = av.x; As[lac + 1][lar] = av.y; As[lac + 2][lar] = av.z; As[lac + 3][lar] = av.w;
        *(float4*)&Bs[lbr][lbc] = *(const float4*)(brow + (size_t)k0 * 1024);
        __syncthreads();
        #pragma unroll
        for (int kk = 0; kk < 16; kk++) {
            float4 a4 = *(const float4*)&As[kk][ty * 4];
            float4 b4 = *(const float4*)&Bs[kk][tx * 4];
            float aa[4] = {a4.x, a4.y, a4.z, a4.w};
            float bb[4] = {b4.x, b4.y, b4.z, b4.w};
            #pragma unroll
            for (int i = 0; i < 4; i++)
                #pragma unroll
                for (int j = 0; j < 4; j++) acc[i][j] += aa[i] * bb[j];
        }
        __syncthreads();
    }
    #pragma unroll
    for (int i = 0; i < 4; i++) {
        float4 w = make_float4(acc[i][0], acc[i][1], acc[i][2], acc[i][3]);
        *(float4*)&out[((size_t)b * N_ + rows[ty * 4 + i]) * D_ + bn * 64 + tx * 4] = w;
    }
}

// ================================================================ null kv prepend (exactly B*H*DH = 4096 threads of work)
__global__ void k_nullfill(const float* __restrict__ nullkv)
{
    int t = blockIdx.x * blockDim.x + threadIdx.x;
    if (t >= B_ * H_ * DH_) return;                  // guard (was the OOB bug)
    int d = t & 63, h = (t >> 6) & 15, b = t >> 10;
    g_k[(((size_t)(b * H_ + h)) * KVR_) * DH_ + d] = nullkv[h * 64 + d];
    g_v[(((size_t)(b * H_ + h)) * KVR_) * DH_ + d] = nullkv[1024 + h * 64 + d];
}

// ================================================================ rotary (thread per (d, d+32) pair)
__global__ void k_rotq(const float* __restrict__ rot)
{
    int t = blockIdx.x * blockDim.x + threadIdx.x;   // 2,097,152
    int d = t & 31, h = (t >> 5) & 15, i = (t >> 9) & 1023, b = t >> 19;
    float* base = g_q + ((size_t)(b * NQ_ + i)) * D_ + h * 64;
    int idx = g_selidx[b * NKV_ + i];
    const float* p = rot + (size_t)idx * 64;
    float p0 = p[d], p1 = p[d + 32];
    float q0 = base[d], q1 = base[d + 32];
    base[d]      = q0 * cosf(p0) - q1 * sinf(p0);
    base[d + 32] = q1 * cosf(p1) + q0 * sinf(p1);
}

__global__ void k_rotk(const float* __restrict__ rot)
{
    int t = blockIdx.x * blockDim.x + threadIdx.x;   // 4,194,304
    int d = t & 31, j = (t >> 5) & 2047, h = (t >> 16) & 15, b = t >> 20;
    float* base = g_k + (((size_t)(b * H_ + h)) * KVR_ + 1 + j) * DH_;
    int idx = g_selidx[(B_ + b) * NKV_ + j];
    const float* p = rot + (size_t)idx * 64;
    float p0 = p[d], p1 = p[d + 32];
    float q0 = base[d], q1 = base[d + 32];
    base[d]      = q0 * cosf(p0) - q1 * sinf(p0);
    base[d + 32] = q1 * cosf(p1) + q0 * sinf(p1);
}

// ================================================================ flash attention, fp32, 64x64 tiles
__global__ __launch_bounds__(256) void k_attn()
{
    extern __shared__ float sm[];
    float* sQt = sm;                 // [d][r]  64x68
    float* sKV = sm + 64 * 68;       // K: [d][c] transposed;  V: [c][dv] natural
    float* sSt = sm + 2 * 64 * 68;   // [c][r]
    float* stm = sm + 3 * 64 * 68;   // m[64]
    float* stl = stm + 64;           // l[64]
    float* sta = stl + 64;           // alpha[64]

    int qt = blockIdx.x, bh = blockIdx.y;
    int b = bh >> 4, h = bh & 15;
    int tid = threadIdx.x;
    int ty = tid >> 4, tx = tid & 15;
    int lr = tid >> 2;              // loader row 0..63
    int lc = (tid & 3) * 16;        // loader col base

    // load Q tile transposed
    {
        const float* src = g_q + ((size_t)(b * NQ_ + qt * 64 + lr)) * D_ + h * 64 + lc;
        #pragma unroll
        for (int u = 0; u < 4; u++) {
            float4 v = *(const float4*)(src + u * 4);
            int d0 = lc + u * 4;
            sQt[(d0 + 0) * 68 + lr] = v.x;
            sQt[(d0 + 1) * 68 + lr] = v.y;
            sQt[(d0 + 2) * 68 + lr] = v.z;
            sQt[(d0 + 3) * 68 + lr] = v.w;
        }
    }
    if (tid < 64) { stm[tid] = -INFINITY; stl[tid] = 0.f; }

    float oacc[4][4] = {};
    const float* kbase = g_k + (size_t)bh * KVR_ * DH_;
    const float* vbase = g_v + (size_t)bh * KVR_ * DH_;

    for (int t = 0; t < 33; t++) {
        // K tile, transposed into smem
        {
            int krow = t * 64 + lr;
            #pragma unroll
            for (int u = 0; u < 4; u++) {
                float4 vv = (krow < KVR_) ? *(const float4*)(kbase + (size_t)krow * 64 + lc + u * 4)
                                          : make_float4(0.f, 0.f, 0.f, 0.f);
                int d0 = lc + u * 4;
                sKV[(d0 + 0) * 68 + lr] = vv.x;
                sKV[(d0 + 1) * 68 + lr] = vv.y;
                sKV[(d0 + 2) * 68 + lr] = vv.z;
                sKV[(d0 + 3) * 68 + lr] = vv.w;
            }
        }
        __syncthreads();

        // S = Q K^T
        float sacc[4][4] = {};
        #pragma unroll
        for (int d = 0; d < 64; d++) {
            float4 a4 = *(const float4*)&sQt[d * 68 + ty * 4];
            float4 b4 = *(const float4*)&sKV[d * 68 + tx * 4];
            float aa[4] = {a4.x, a4.y, a4.z, a4.w};
            float bb[4] = {b4.x, b4.y, b4.z, b4.w};
            #pragma unroll
            for (int i = 0; i < 4; i++)
                #pragma unroll
                for (int j = 0; j < 4; j++) sacc[i][j] += aa[i] * bb[j];
        }
        // store scaled + masked scores transposed: sSt[c][r]
        #pragma unroll
        for (int j = 0; j < 4; j++) {
            int c = tx * 4 + j;
            bool valid = (t * 64 + c) < KVR_;
            float4 w;
            w.x = valid ? sacc[0][j] * 0.125f : -INFINITY;
            w.y = valid ? sacc[1][j] * 0.125f : -INFINITY;
            w.z = valid ? sacc[2][j] * 0.125f : -INFINITY;
            w.w = valid ? sacc[3][j] * 0.125f : -INFINITY;
            *(float4*)&sSt[c * 68 + ty * 4] = w;
        }
        __syncthreads();

        // online softmax: 4 threads per row
        {
            int r = lr;
            float mo = stm[r];
            float tm = -INFINITY;
            #pragma unroll
            for (int u = 0; u < 16; u++) tm = fmaxf(tm, sSt[(lc + u) * 68 + r]);
            tm = fmaxf(tm, __shfl_xor_sync(0xffffffffu, tm, 1));
            tm = fmaxf(tm, __shfl_xor_sync(0xffffffffu, tm, 2));
            float nm = fmaxf(mo, tm);
            float sum = 0.f;
            #pragma unroll
            for (int u = 0; u < 16; u++) {
                float p = expf(sSt[(lc + u) * 68 + r] - nm);
                sSt[(lc + u) * 68 + r] = p;
                sum += p;
            }
            sum += __shfl_xor_sync(0xffffffffu, sum, 1);
            sum += __shfl_xor_sync(0xffffffffu, sum, 2);
            if ((tid & 3) == 0) {
                float alpha = expf(mo - nm);
                stl[r] = stl[r] * alpha + sum;
                stm[r] = nm;
                sta[r] = alpha;
            }
        }
        __syncthreads();

        // rescale accumulators
        #pragma unroll
        for (int i = 0; i < 4; i++) {
            float al = sta[ty * 4 + i];
            #pragma unroll
            for (int j = 0; j < 4; j++) oacc[i][j] *= al;
        }
        // V tile, natural [c][dv] layout (overwrites K)
        {
            int vrow = t * 64 + lr;
            #pragma unroll
            for (int u = 0; u < 4; u++) {
                float4 vv = (vrow < KVR_) ? *(const float4*)(vbase + (size_t)vrow * 64 + lc + u * 4)
                                          : make_float4(0.f, 0.f, 0.f, 0.f);
                *(float4*)&sKV[lr * 68 + lc + u * 4] = vv;
            }
        }
        __syncthreads();

        // O += P V
        #pragma unroll
        for (int c = 0; c < 64; c++) {
            float4 a4 = *(const float4*)&sSt[c * 68 + ty * 4];
            float4 b4 = *(const float4*)&sKV[c * 68 + tx * 4];
            float aa[4] = {a4.x, a4.y, a4.z, a4.w};
            float bb[4] = {b4.x, b4.y, b4.z, b4.w};
            #pragma unroll
            for (int i = 0; i < 4; i++)
                #pragma unroll
                for (int j = 0; j < 4; j++) oacc[i][j] += aa[i] * bb[j];
        }
        __syncthreads();
    }

    #pragma unroll
    for (int i = 0; i < 4; i++) {
        int r = ty * 4 + i;
        float inv = 1.f / stl[r];
        float4 w = make_float4(oacc[i][0] * inv, oacc[i][1] * inv, oacc[i][2] * inv, oacc[i][3] * inv);
        *(float4*)&g_ao[((size_t)(b * NQ_ + qt * 64 + r)) * D_ + h * 64 + tx * 4] = w;
    }
}

// ================================================================ launch
extern "C" void kernel_launch(void* const* d_in, const int* in_sizes, int n_in,
                              void* d_out, int out_size)
{
    (void)in_sizes; (void)n_in; (void)out_size;
    const float* x       = (const float*)d_in[0];
    const float* rot     = (const float*)d_in[1];
    const float* wrq     = (const float*)d_in[2];
    const float* wrkv    = (const float*)d_in[3];
    const float* wq      = (const float*)d_in[4];
    const float* wkv     = (const float*)d_in[5];
    const float* wout    = (const float*)d_in[6];
    const float* nullkv  = (const float*)d_in[7];
    const float* nulltok = (const float*)d_in[8];
    float* out = (float*)d_out;

    cudaFuncSetAttribute(k_attn, cudaFuncAttributeMaxDynamicSharedMemorySize, 3 * 64 * 68 * 4 + 3 * 64 * 4);

    k_fillout<<<8192, 256>>>((float4*)out, nulltok);
    k_router <<<4096, 256>>>(x, wrq, wrkv);
    k_coorsel<<<8, 1024>>>();
    k_qproj  <<<dim3(16, 16, 4), 256>>>(x, wq);
    k_kvproj <<<dim3(32, 32, 4), 256>>>(x, wkv);
    k_nullfill<<<16, 256>>>(nullkv);
    k_rotq   <<<8192, 256>>>(rot);
    k_rotk   <<<16384, 256>>>(rot);
    k_attn   <<<dim3(16, 64), 256, 3 * 64 * 68 * 4 + 3 * 64 * 4>>>();
    k_outproj<<<dim3(16, 16, 4), 256>>>(wout, out);
}

// round 17
// speedup vs baseline: 1.0822x; 1.0822x over previous
#include <cuda_runtime.h>
#include <math.h>
#include <stdint.h>

#define B_   4
#define N_   8192
#define D_   1024
#define H_   16
#define DH_  64
#define NQ_  1024
#define NKV_ 2048
#define KVR_ 2049   // NKV + 1 null row

// ---------------------------------------------------------------- device scratch (no allocations allowed)
__device__ float g_logits[2 * B_ * N_];          // [router][b][n]
__device__ int   g_selidx[2 * B_ * NKV_];        // [router][b][k] (router 0 uses first NQ_)
__device__ float g_q [B_ * NQ_ * D_];            // [b][i][h*64+d], rotary applied in place
__device__ float g_k [B_ * H_ * KVR_ * DH_];     // [b*16+h][row][d], row 0 = null
__device__ float g_v [B_ * H_ * KVR_ * DH_];
__device__ float g_ao[B_ * NQ_ * D_];            // attention output [b][i][h*64+d]

// ---------------------------------------------------------------- fast exp on FMA pipe (no MUFU)
// exp(x) for x <= 0; relative error ~1e-7. Degree-6 poly for 2^f, f in [-0.5,0.5].
__device__ __forceinline__ float fexp(float x)
{
    x = fmaxf(x, -87.0f);                      // -inf-safe; exp(-87) ~ 1.6e-38 ~ 0
    float t  = x * 1.4426950408889634f;        // x * log2(e)
    float fi = __fadd_rn(t, 12582912.0f);      // round-to-nearest via 1.5*2^23
    float n  = __fadd_rn(fi, -12582912.0f);
    float f  = t - n;
    int   ni = __float_as_int(fi) - 0x4B400000;
    float p  = 1.5403530e-4f;
    p = fmaf(p, f, 1.3333558e-3f);
    p = fmaf(p, f, 9.6181291e-3f);
    p = fmaf(p, f, 5.5504109e-2f);
    p = fmaf(p, f, 2.4022651e-1f);
    p = fmaf(p, f, 6.9314718e-1f);
    p = fmaf(p, f, 1.0f);
    return p * __int_as_float((ni + 127) << 23);
}

// ================================================================ 1. router logits (warp per token, both routers)
__global__ __launch_bounds__(256) void k_router(const float* __restrict__ x,
                                                const float* __restrict__ wrq,
                                                const float* __restrict__ wrk)
{
    int gw   = (blockIdx.x * blockDim.x + threadIdx.x) >> 5;
    int lane = threadIdx.x & 31;
    if (gw >= B_ * N_) return;
    const float4* xr  = (const float4*)(x + (size_t)gw * D_);
    const float4* wq4 = (const float4*)wrq;
    const float4* wk4 = (const float4*)wrk;
    float aq = 0.f, ak = 0.f;
    #pragma unroll 4
    for (int i = lane; i < D_ / 4; i += 32) {
        float4 xv = xr[i], q = wq4[i], k = wk4[i];
        aq += xv.x * q.x + xv.y * q.y + xv.z * q.z + xv.w * q.w;
        ak += xv.x * k.x + xv.y * k.y + xv.z * k.z + xv.w * k.w;
    }
    #pragma unroll
    for (int o = 16; o; o >>= 1) {
        aq += __shfl_xor_sync(0xffffffffu, aq, o);
        ak += __shfl_xor_sync(0xffffffffu, ak, o);
    }
    if (!lane) { g_logits[gw] = aq; g_logits[B_ * N_ + gw] = ak; }
}

// ================================================================ 2. coordinate descent + exact top-k selection
__global__ __launch_bounds__(1024) void k_coorsel()
{
    __shared__ __align__(16) unsigned char smraw[49152];
    unsigned int*   skey = (unsigned int*)smraw;
    unsigned short* sidx = (unsigned short*)(smraw + 32768);
    float*          red  = (float*)smraw;

    int r = blockIdx.x >> 2;
    int b = blockIdx.x & 3;
    int ksel = r ? NKV_ : NQ_;
    int keff = r ? 2304 : 1152;
    float cst = 0.1f * logf((float)keff);
    const float* lg = g_logits + ((size_t)r * B_ + b) * N_;
    int t = threadIdx.x;

    float sreg[8], breg[8];
    #pragma unroll
    for (int j = 0; j < 8; j++) { float v = lg[t + j * 1024]; sreg[j] = v; breg[j] = -v; }

    float a = 0.f;
    for (int it = 0; it < 20; it++) {
        float arg[8];
        float mloc = -INFINITY;
        #pragma unroll
        for (int j = 0; j < 8; j++) { arg[j] = (sreg[j] + breg[j]) / 0.1f; mloc = fmaxf(mloc, arg[j]); }
        #pragma unroll
        for (int o = 16; o; o >>= 1) mloc = fmaxf(mloc, __shfl_xor_sync(0xffffffffu, mloc, o));
        if (!(t & 31)) red[t >> 5] = mloc;
        __syncthreads();
        if (t < 32) {
            float v = red[t];
            #pragma unroll
            for (int o = 16; o; o >>= 1) v = fmaxf(v, __shfl_xor_sync(0xffffffffu, v, o));
            if (!t) red[32] = v;
        }
        __syncthreads();
        float m = red[32];
        __syncthreads();

        float sl = 0.f;
        #pragma unroll
        for (int j = 0; j < 8; j++) sl += expf(arg[j] - m);
        #pragma unroll
        for (int o = 16; o; o >>= 1) sl += __shfl_xor_sync(0xffffffffu, sl, o);
        if (!(t & 31)) red[t >> 5] = sl;
        __syncthreads();
        if (t < 32) {
            float v = red[t];
            #pragma unroll
            for (int o = 16; o; o >>= 1) v += __shfl_xor_sync(0xffffffffu, v, o);
            if (!t) red[32] = v;
        }
        __syncthreads();
        float sum = red[32];
        __syncthreads();

        a = cst - 0.1f * (logf(sum) + m);
        #pragma unroll
        for (int j = 0; j < 8; j++) breg[j] = -fmaxf(sreg[j] + a, 0.f);
    }

    #pragma unroll
    for (int j = 0; j < 8; j++) {
        float sc = expf(((sreg[j] + a) + breg[j]) / 0.1f);
        int gi = t + j * 1024;
        skey[gi] = __float_as_uint(sc);
        sidx[gi] = (unsigned short)gi;
    }
    __syncthreads();

    for (int k = 2; k <= 8192; k <<= 1) {
        for (int jj = k >> 1; jj > 0; jj >>= 1) {
            for (int i = t; i < 8192; i += 1024) {
                int ixj = i ^ jj;
                if (ixj > i) {
                    unsigned int   k1 = skey[i], k2 = skey[ixj];
                    unsigned short i1 = sidx[i], i2 = sidx[ixj];
                    bool gt2 = (k2 > k1) || (k2 == k1 && i2 < i1);
                    if (gt2 == ((i & k) == 0)) {
                        skey[i] = k2; skey[ixj] = k1;
                        sidx[i] = i2; sidx[ixj] = i1;
                    }
                }
            }
            __syncthreads();
        }
    }

    int* dst = g_selidx + ((size_t)r * B_ + b) * NKV_;
    for (int i = t; i < ksel; i += 1024) dst[i] = (int)sidx[i];
}

// ================================================================ 3. fill output with null tokens
__global__ void k_fillout(float4* __restrict__ out4, const float* __restrict__ nt)
{
    const float4* nt4 = (const float4*)nt;
    int total = B_ * N_ * (D_ / 4);
    for (int i = blockIdx.x * blockDim.x + threadIdx.x; i < total; i += gridDim.x * blockDim.x)
        out4[i] = nt4[i & 255];
}

// ================================================================ GEMM: 128x128 tile, BK=8, double-buffered, 8x8/thread
// shared mainloop body (aptr: per-thread A row pointer at k-offset akc; bptr: B at [brow][bn*128+bcol])
#define GEMM_MAIN(LDB)                                                         \
    {                                                                          \
        float4 av = *(const float4*)aptr;                                      \
        float4 bv = *(const float4*)bptr;                                      \
        As[0][akc+0][arow]=av.x; As[0][akc+1][arow]=av.y;                      \
        As[0][akc+2][arow]=av.z; As[0][akc+3][arow]=av.w;                      \
        *(float4*)&Bs[0][brow][bcol] = bv;                                     \
    }                                                                          \
    __syncthreads();                                                           \
    int buf = 0;                                                               \
    for (int k0 = 0; k0 < 1024; k0 += 8) {                                     \
        bool more = (k0 + 8) < 1024;                                           \
        float4 pa, pb;                                                         \
        if (more) {                                                            \
            pa = *(const float4*)(aptr + k0 + 8);                              \
            pb = *(const float4*)(bptr + (size_t)(k0 + 8) * (LDB));            \
        }                                                                      \
        _Pragma("unroll")                                                      \
        for (int kk = 0; kk < 8; kk++) {                                       \
            float4 a0 = *(const float4*)&As[buf][kk][ty*8];                    \
            float4 a1 = *(const float4*)&As[buf][kk][ty*8+4];                  \
            float4 b0 = *(const float4*)&Bs[buf][kk][tx*8];                    \
            float4 b1 = *(const float4*)&Bs[buf][kk][tx*8+4];                  \
            float aa[8]={a0.x,a0.y,a0.z,a0.w,a1.x,a1.y,a1.z,a1.w};             \
            float bb[8]={b0.x,b0.y,b0.z,b0.w,b1.x,b1.y,b1.z,b1.w};             \
            _Pragma("unroll")                                                  \
            for (int i = 0; i < 8; i++)                                        \
                _Pragma("unroll")                                              \
                for (int j = 0; j < 8; j++)                                    \
                    acc[i][j] = fmaf(aa[i], bb[j], acc[i][j]);                 \
        }                                                                      \
        if (more) {                                                            \
            As[buf^1][akc+0][arow]=pa.x; As[buf^1][akc+1][arow]=pa.y;          \
            As[buf^1][akc+2][arow]=pa.z; As[buf^1][akc+3][arow]=pa.w;          \
            *(float4*)&Bs[buf^1][brow][bcol] = pb;                             \
        }                                                                      \
        buf ^= 1;                                                              \
        __syncthreads();                                                       \
    }

__global__ __launch_bounds__(256) void k_qproj(const float* __restrict__ x, const float* __restrict__ wq)
{
    __shared__ float As[2][8][132];
    __shared__ float Bs[2][8][132];
    __shared__ int rows[128];
    int bn = blockIdx.x, bm = blockIdx.y, b = blockIdx.z;
    int tid = threadIdx.x;
    int tx = tid & 15, ty = tid >> 4;
    if (tid < 128) rows[tid] = g_selidx[b * NKV_ + bm * 128 + tid];
    __syncthreads();
    int arow = tid >> 1, akc = (tid & 1) * 4;
    int brow = tid >> 5, bcol = (tid & 31) * 4;
    const float* aptr = x + ((size_t)b * N_ + rows[arow]) * D_ + akc;
    const float* bptr = wq + (size_t)brow * 1024 + bn * 128 + bcol;
    float acc[8][8] = {};
    GEMM_MAIN(1024)
    #pragma unroll
    for (int i = 0; i < 8; i++) {
        float* dst = &g_q[((size_t)(b * NQ_ + bm * 128 + ty * 8 + i)) * D_ + bn * 128 + tx * 8];
        *(float4*)dst       = make_float4(acc[i][0], acc[i][1], acc[i][2], acc[i][3]);
        *(float4*)(dst + 4) = make_float4(acc[i][4], acc[i][5], acc[i][6], acc[i][7]);
    }
}

__global__ __launch_bounds__(256) void k_kvproj(const float* __restrict__ x, const float* __restrict__ wkv)
{
    __shared__ float As[2][8][132];
    __shared__ float Bs[2][8][132];
    __shared__ int rows[128];
    int bn = blockIdx.x, bm = blockIdx.y, b = blockIdx.z;
    int tid = threadIdx.x;
    int tx = tid & 15, ty = tid >> 4;
    if (tid < 128) rows[tid] = g_selidx[(B_ + b) * NKV_ + bm * 128 + tid];
    __syncthreads();
    int arow = tid >> 1, akc = (tid & 1) * 4;
    int brow = tid >> 5, bcol = (tid & 31) * 4;
    const float* aptr = x + ((size_t)b * N_ + rows[arow]) * D_ + akc;
    const float* bptr = wkv + (size_t)brow * 2048 + bn * 128 + bcol;
    float acc[8][8] = {};
    GEMM_MAIN(2048)
    int e0 = bn * 128 + tx * 8;
    int s = e0 >> 10, h = (e0 >> 6) & 15, d0 = e0 & 63;
    float* dstm = s ? g_v : g_k;
    #pragma unroll
    for (int i = 0; i < 8; i++) {
        float* dst = &dstm[(((size_t)(b * H_ + h)) * KVR_ + 1 + bm * 128 + ty * 8 + i) * DH_ + d0];
        *(float4*)dst       = make_float4(acc[i][0], acc[i][1], acc[i][2], acc[i][3]);
        *(float4*)(dst + 4) = make_float4(acc[i][4], acc[i][5], acc[i][6], acc[i][7]);
    }
}

__global__ __launch_bounds__(256) void k_outproj(const float* __restrict__ wout, float* __restrict__ out)
{
    __shared__ float As[2][8][132];
    __shared__ float Bs[2][8][132];
    __shared__ int rows[128];
    int bn = blockIdx.x, bm = blockIdx.y, b = blockIdx.z;
    int tid = threadIdx.x;
    int tx = tid & 15, ty = tid >> 4;
    if (tid < 128) rows[tid] = g_selidx[b * NKV_ + bm * 128 + tid];
    __syncthreads();
    int arow = tid >> 1, akc = (tid & 1) * 4;
    int brow = tid >> 5, bcol = (tid & 31) * 4;
    const float* aptr = g_ao + ((size_t)(b * NQ_ + bm * 128 + arow)) * D_ + akc;
    const float* bptr = wout + (size_t)brow * 1024 + bn * 128 + bcol;
    float acc[8][8] = {};
    GEMM_MAIN(1024)
    #pragma unroll
    for (int i = 0; i < 8; i++) {
        float* dst = &out[((size_t)b * N_ + rows[ty * 8 + i]) * D_ + bn * 128 + tx * 8];
        *(float4*)dst       = make_float4(acc[i][0], acc[i][1], acc[i][2], acc[i][3]);
        *(float4*)(dst + 4) = make_float4(acc[i][4], acc[i][5], acc[i][6], acc[i][7]);
    }
}

// ================================================================ null kv prepend
__global__ void k_nullfill(const float* __restrict__ nullkv)
{
    int t = blockIdx.x * blockDim.x + threadIdx.x;
    if (t >= B_ * H_ * DH_) return;
    int d = t & 63, h = (t >> 6) & 15, b = t >> 10;
    g_k[(((size_t)(b * H_ + h)) * KVR_) * DH_ + d] = nullkv[h * 64 + d];
    g_v[(((size_t)(b * H_ + h)) * KVR_) * DH_ + d] = nullkv[1024 + h * 64 + d];
}

// ================================================================ rotary
__global__ void k_rotq(const float* __restrict__ rot)
{
    int t = blockIdx.x * blockDim.x + threadIdx.x;
    int d = t & 31, h = (t >> 5) & 15, i = (t >> 9) & 1023, b = t >> 19;
    float* base = g_q + ((size_t)(b * NQ_ + i)) * D_ + h * 64;
    int idx = g_selidx[b * NKV_ + i];
    const float* p = rot + (size_t)idx * 64;
    float p0 = p[d], p1 = p[d + 32];
    float q0 = base[d], q1 = base[d + 32];
    base[d]      = q0 * cosf(p0) - q1 * sinf(p0);
    base[d + 32] = q1 * cosf(p1) + q0 * sinf(p1);
}

__global__ void k_rotk(const float* __restrict__ rot)
{
    int t = blockIdx.x * blockDim.x + threadIdx.x;
    int d = t & 31, j = (t >> 5) & 2047, h = (t >> 16) & 15, b = t >> 20;
    float* base = g_k + (((size_t)(b * H_ + h)) * KVR_ + 1 + j) * DH_;
    int idx = g_selidx[(B_ + b) * NKV_ + j];
    const float* p = rot + (size_t)idx * 64;
    float p0 = p[d], p1 = p[d + 32];
    float q0 = base[d], q1 = base[d + 32];
    base[d]      = q0 * cosf(p0) - q1 * sinf(p0);
    base[d + 32] = q1 * cosf(p1) + q0 * sinf(p1);
}

// ================================================================ flash attention: 128 q x 64 kv tiles, 8x4 micro, poly exp
__global__ __launch_bounds__(256) void k_attn()
{
    extern __shared__ float sm[];
    float* sQt = sm;             // [64 d][132] q rows 128 (transposed)
    float* sKV = sm + 8448;      // K^T [64 d][68 c]  /  V [64 c][68 d]
    float* sSt = sm + 12800;     // [64 c][132 r]
    float* stm = sm + 21248;     // m[128]
    float* stl = stm + 128;      // l[128]
    float* sta = stl + 128;      // alpha[128]

    int qt = blockIdx.x, bh = blockIdx.y;
    int b = bh >> 4, h = bh & 15;
    int tid = threadIdx.x;
    int tx = tid & 15, ty = tid >> 4;
    int lr = tid >> 2, lc = (tid & 3) * 16;

    // Q tile: 128 rows x 64 d, transposed
    #pragma unroll
    for (int rr = lr; rr < 128; rr += 64) {
        const float* src = g_q + ((size_t)(b * NQ_ + qt * 128 + rr)) * D_ + h * 64 + lc;
        #pragma unroll
        for (int u = 0; u < 4; u++) {
            float4 v = *(const float4*)(src + u * 4);
            int d0 = lc + u * 4;
            sQt[(d0 + 0) * 132 + rr] = v.x;
            sQt[(d0 + 1) * 132 + rr] = v.y;
            sQt[(d0 + 2) * 132 + rr] = v.z;
            sQt[(d0 + 3) * 132 + rr] = v.w;
        }
    }
    if (tid < 128) { stm[tid] = -INFINITY; stl[tid] = 0.f; }

    float oacc[8][4] = {};
    const float* kbase = g_k + (size_t)bh * KVR_ * DH_;
    const float* vbase = g_v + (size_t)bh * KVR_ * DH_;

    for (int kt = 0; kt < 33; kt++) {
        // K tile (64 rows), transposed [d][c]
        {
            int krow = kt * 64 + lr;
            #pragma unroll
            for (int u = 0; u < 4; u++) {
                float4 vv = (krow < KVR_) ? *(const float4*)(kbase + (size_t)krow * 64 + lc + u * 4)
                                          : make_float4(0.f, 0.f, 0.f, 0.f);
                int d0 = lc + u * 4;
                sKV[(d0 + 0) * 68 + lr] = vv.x;
                sKV[(d0 + 1) * 68 + lr] = vv.y;
                sKV[(d0 + 2) * 68 + lr] = vv.z;
                sKV[(d0 + 3) * 68 + lr] = vv.w;
            }
        }
        __syncthreads();

        // S = Q K^T  (8 rows x 4 cols per thread)
        float sacc[8][4] = {};
        #pragma unroll 8
        for (int d = 0; d < 64; d++) {
            float4 a0 = *(const float4*)&sQt[d * 132 + ty * 8];
            float4 a1 = *(const float4*)&sQt[d * 132 + ty * 8 + 4];
            float4 b0 = *(const float4*)&sKV[d * 68 + tx * 4];
            float aa[8] = {a0.x, a0.y, a0.z, a0.w, a1.x, a1.y, a1.z, a1.w};
            float bb[4] = {b0.x, b0.y, b0.z, b0.w};
            #pragma unroll
            for (int i = 0; i < 8; i++)
                #pragma unroll
                for (int j = 0; j < 4; j++)
                    sacc[i][j] = fmaf(aa[i], bb[j], sacc[i][j]);
        }
        // scores transposed [c][r], scaled + masked
        #pragma unroll
        for (int j = 0; j < 4; j++) {
            int c = tx * 4 + j;
            bool valid = (kt * 64 + c) < KVR_;
            float4 w0, w1;
            w0.x = valid ? sacc[0][j] * 0.125f : -INFINITY;
            w0.y = valid ? sacc[1][j] * 0.125f : -INFINITY;
            w0.z = valid ? sacc[2][j] * 0.125f : -INFINITY;
            w0.w = valid ? sacc[3][j] * 0.125f : -INFINITY;
            w1.x = valid ? sacc[4][j] * 0.125f : -INFINITY;
            w1.y = valid ? sacc[5][j] * 0.125f : -INFINITY;
            w1.z = valid ? sacc[6][j] * 0.125f : -INFINITY;
            w1.w = valid ? sacc[7][j] * 0.125f : -INFINITY;
            *(float4*)&sSt[c * 132 + ty * 8]     = w0;
            *(float4*)&sSt[c * 132 + ty * 8 + 4] = w1;
        }
        __syncthreads();

        // V tile load (overwrites K region; K reads completed before last sync)
        {
            int vrow = kt * 64 + lr;
            #pragma unroll
            for (int u = 0; u < 4; u++) {
                float4 vv = (vrow < KVR_) ? *(const float4*)(vbase + (size_t)vrow * 64 + lc + u * 4)
                                          : make_float4(0.f, 0.f, 0.f, 0.f);
                *(float4*)&sKV[lr * 68 + lc + u * 4] = vv;
            }
        }
        // online softmax: 2 threads per row, 32 cols each; exp on FMA pipe
        {
            int r  = tid >> 1;
            int cp = (tid & 1) * 32;
            float mo = stm[r];
            float tm = -INFINITY;
            #pragma unroll
            for (int u = 0; u < 32; u++) tm = fmaxf(tm, sSt[(cp + u) * 132 + r]);
            tm = fmaxf(tm, __shfl_xor_sync(0xffffffffu, tm, 1));
            float nm = fmaxf(mo, tm);
            float sum = 0.f;
            #pragma unroll
            for (int u = 0; u < 32; u++) {
                float p = fexp(sSt[(cp + u) * 132 + r] - nm);
                sSt[(cp + u) * 132 + r] = p;
                sum += p;
            }
            sum += __shfl_xor_sync(0xffffffffu, sum, 1);
            if (!(tid & 1)) {
                float alpha = fexp(mo - nm);
                stl[r] = stl[r] * alpha + sum;
                stm[r] = nm;
                sta[r] = alpha;
            }
        }
        __syncthreads();

        // rescale + O += P V
        #pragma unroll
        for (int i = 0; i < 8; i++) {
            float al = sta[ty * 8 + i];
            #pragma unroll
            for (int j = 0; j < 4; j++) oacc[i][j] *= al;
        }
        #pragma unroll 8
        for (int c = 0; c < 64; c++) {
            float4 a0 = *(const float4*)&sSt[c * 132 + ty * 8];
            float4 a1 = *(const float4*)&sSt[c * 132 + ty * 8 + 4];
            float4 b0 = *(const float4*)&sKV[c * 68 + tx * 4];
            float aa[8] = {a0.x, a0.y, a0.z, a0.w, a1.x, a1.y, a1.z, a1.w};
            float bb[4] = {b0.x, b0.y, b0.z, b0.w};
            #pragma unroll
            for (int i = 0; i < 8; i++)
                #pragma unroll
                for (int j = 0; j < 4; j++)
                    oacc[i][j] = fmaf(aa[i], bb[j], oacc[i][j]);
        }
        __syncthreads();
    }

    #pragma unroll
    for (int i = 0; i < 8; i++) {
        int r = ty * 8 + i;
        float inv = 1.f / stl[r];
        float4 w = make_float4(oacc[i][0] * inv, oacc[i][1] * inv, oacc[i][2] * inv, oacc[i][3] * inv);
        *(float4*)&g_ao[((size_t)(b * NQ_ + qt * 128 + r)) * D_ + h * 64 + tx * 4] = w;
    }
}

// ================================================================ launch
extern "C" void kernel_launch(void* const* d_in, const int* in_sizes, int n_in,
                              void* d_out, int out_size)
{
    (void)in_sizes; (void)n_in; (void)out_size;
    const float* x       = (const float*)d_in[0];
    const float* rot     = (const float*)d_in[1];
    const float* wrq     = (const float*)d_in[2];
    const float* wrkv    = (const float*)d_in[3];
    const float* wq      = (const float*)d_in[4];
    const float* wkv     = (const float*)d_in[5];
    const float* wout    = (const float*)d_in[6];
    const float* nullkv  = (const float*)d_in[7];
    const float* nulltok = (const float*)d_in[8];
    float* out = (float*)d_out;

    const int attn_smem = (8448 + 4352 + 8448 + 3 * 128) * 4;   // 86528 B
    cudaFuncSetAttribute(k_attn, cudaFuncAttributeMaxDynamicSharedMemorySize, attn_smem);

    k_fillout <<<8192, 256>>>((float4*)out, nulltok);
    k_router  <<<4096, 256>>>(x, wrq, wrkv);
    k_coorsel <<<8, 1024>>>();
    k_qproj   <<<dim3(8, 8, 4), 256>>>(x, wq);
    k_kvproj  <<<dim3(16, 16, 4), 256>>>(x, wkv);
    k_nullfill<<<16, 256>>>(nullkv);
    k_rotq    <<<8192, 256>>>(rot);
    k_rotk    <<<16384, 256>>>(rot);
    k_attn    <<<dim3(8, 64), 256, attn_smem>>>();
    k_outproj <<<dim3(8, 8, 4), 256>>>(wout, out);
}